// round 4
// baseline (speedup 1.0000x reference)
#include <cuda_runtime.h>
#include <cuda_bf16.h>
#include <cstdint>
#include <math.h>

// ---------------------------------------------------------------------------
// Problem constants
// ---------------------------------------------------------------------------
static constexpr int B_ = 8;
static constexpr int K_ = 2048;   // time / contraction dim
static constexpr int D_ = 1024;   // channel dim
static constexpr int CHUNKS = 16; // time chunks == t-tiles (BM)
static constexpr int T_ = K_ / CHUNKS;  // 128 == BM

// GEMM tiling: C[t, d] = sum_k W[t,k] * x[k,d]   per batch
static constexpr int BM = 128;   // t tile
static constexpr int BN = 128;   // d tile
static constexpr int BK = 32;    // k per stage
static constexpr int NSTAGE_IT = K_ / BK;  // 64
static constexpr int NSTAGES = 4;          // pipeline depth

// smem strides (bytes), padded for conflict-free ldmatrix
static constexpr int W_STRIDE = 80;    // 32 bf16 = 64B + 16B pad
static constexpr int X_STRIDE = 272;   // 128 bf16 = 256B + 16B pad
static constexpr int W_TILE_B = BM * W_STRIDE;        // 10240
static constexpr int X_TILE_B = BK * X_STRIDE;        // 8704
static constexpr int STAGE_B = 2 * W_TILE_B + 2 * X_TILE_B;  // 37888
static constexpr int SMEM_TOTAL = NSTAGES * STAGE_B;         // 151552

// epilogue smem reuse: lam tile [128][132] fp32 + AU scratch
static constexpr int LAM_STRIDE = 132;                       // floats
static constexpr int LAM_BYTES = BM * LAM_STRIDE * 4;        // 67584
static_assert(LAM_BYTES + 1024 <= SMEM_TOTAL, "epilogue fits");

// ---------------------------------------------------------------------------
// Device scratch (no cudaMalloc allowed)
// ---------------------------------------------------------------------------
__device__ __align__(256) __nv_bfloat16 g_Whi[(size_t)K_ * K_];
__device__ __align__(256) __nv_bfloat16 g_Wlo[(size_t)K_ * K_];
__device__ __align__(256) __nv_bfloat16 g_xhi[(size_t)B_ * K_ * D_];
__device__ __align__(256) __nv_bfloat16 g_xlo[(size_t)B_ * K_ * D_];
__device__ __align__(256) float g_lam[(size_t)B_ * K_ * D_];
__device__ __align__(256) float g_A[(size_t)B_ * CHUNKS * D_];
__device__ __align__(256) float g_U[(size_t)B_ * CHUNKS * D_];
__device__ __align__(256) float g_carry[(size_t)B_ * CHUNKS * D_];

// ---------------------------------------------------------------------------
// PTX helpers (baseline ISA only — target sm_103 has no 'a' features)
// ---------------------------------------------------------------------------
__device__ __forceinline__ uint32_t smem_u32(const void* p) {
    uint32_t a;
    asm("{ .reg .u64 t; cvta.to.shared.u64 t, %1; cvt.u32.u64 %0, t; }"
        : "=r"(a) : "l"(p));
    return a;
}

__device__ __forceinline__ void cp_async16(uint32_t dst, const void* src) {
    asm volatile("cp.async.cg.shared.global [%0], [%1], 16;"
                 :: "r"(dst), "l"(src));
}

__device__ __forceinline__ void ldm_x4(uint32_t* r, uint32_t addr) {
    asm volatile("ldmatrix.sync.aligned.m8n8.x4.shared.b16 {%0,%1,%2,%3}, [%4];"
                 : "=r"(r[0]), "=r"(r[1]), "=r"(r[2]), "=r"(r[3]) : "r"(addr));
}

__device__ __forceinline__ void ldm_x4_t(uint32_t* r, uint32_t addr) {
    asm volatile("ldmatrix.sync.aligned.m8n8.x4.trans.shared.b16 {%0,%1,%2,%3}, [%4];"
                 : "=r"(r[0]), "=r"(r[1]), "=r"(r[2]), "=r"(r[3]) : "r"(addr));
}

__device__ __forceinline__ void mma_bf16(float* c, const uint32_t* a,
                                         const uint32_t b0, const uint32_t b1) {
    asm volatile(
        "mma.sync.aligned.m16n8k16.row.col.f32.bf16.bf16.f32 "
        "{%0,%1,%2,%3}, {%4,%5,%6,%7}, {%8,%9}, {%0,%1,%2,%3};"
        : "+f"(c[0]), "+f"(c[1]), "+f"(c[2]), "+f"(c[3])
        : "r"(a[0]), "r"(a[1]), "r"(a[2]), "r"(a[3]), "r"(b0), "r"(b1));
}

// ---------------------------------------------------------------------------
// Convert W fp32 -> bf16 hi/lo
// ---------------------------------------------------------------------------
__global__ void convert_W_kernel(const float* __restrict__ W) {
    const size_t i = ((size_t)blockIdx.x * blockDim.x + threadIdx.x) * 4;
    float4 v = *reinterpret_cast<const float4*>(W + i);
    __nv_bfloat16 h[4], l[4];
    h[0] = __float2bfloat16(v.x); l[0] = __float2bfloat16(v.x - __bfloat162float(h[0]));
    h[1] = __float2bfloat16(v.y); l[1] = __float2bfloat16(v.y - __bfloat162float(h[1]));
    h[2] = __float2bfloat16(v.z); l[2] = __float2bfloat16(v.z - __bfloat162float(h[2]));
    h[3] = __float2bfloat16(v.w); l[3] = __float2bfloat16(v.w - __bfloat162float(h[3]));
    *reinterpret_cast<uint2*>(g_Whi + i) = *reinterpret_cast<uint2*>(h);
    *reinterpret_cast<uint2*>(g_Wlo + i) = *reinterpret_cast<uint2*>(l);
}

// Convert x fp32 -> bf16 hi/lo (same layout, no transpose)
__global__ void convert_x_kernel(const float* __restrict__ x) {
    const size_t i = ((size_t)blockIdx.x * blockDim.x + threadIdx.x) * 4;
    float4 v = *reinterpret_cast<const float4*>(x + i);
    __nv_bfloat16 h[4], l[4];
    h[0] = __float2bfloat16(v.x); l[0] = __float2bfloat16(v.x - __bfloat162float(h[0]));
    h[1] = __float2bfloat16(v.y); l[1] = __float2bfloat16(v.y - __bfloat162float(h[1]));
    h[2] = __float2bfloat16(v.z); l[2] = __float2bfloat16(v.z - __bfloat162float(h[2]));
    h[3] = __float2bfloat16(v.w); l[3] = __float2bfloat16(v.w - __bfloat162float(h[3]));
    *reinterpret_cast<uint2*>(g_xhi + i) = *reinterpret_cast<uint2*>(h);
    *reinterpret_cast<uint2*>(g_xlo + i) = *reinterpret_cast<uint2*>(l);
}

// ---------------------------------------------------------------------------
// GEMM + sigmoid + fused per-chunk scan summary
// ---------------------------------------------------------------------------
__device__ __forceinline__ void load_stage(uint32_t sbase,
                                           const __nv_bfloat16* Wh,
                                           const __nv_bfloat16* Wl,
                                           const __nv_bfloat16* xh,
                                           const __nv_bfloat16* xl,
                                           int k0, int tid) {
    // W tiles: 128 rows x 4 segs of 16B
    #pragma unroll
    for (int u = tid; u < 512; u += 256) {
        const int row = u >> 2, seg = u & 3;
        const uint32_t off = (uint32_t)(row * W_STRIDE + seg * 16);
        const __nv_bfloat16* gh = Wh + (size_t)row * K_ + k0 + seg * 8;
        const __nv_bfloat16* gl = Wl + (size_t)row * K_ + k0 + seg * 8;
        cp_async16(sbase + off, gh);
        cp_async16(sbase + W_TILE_B + off, gl);
    }
    // x tiles: 32 rows x 16 segs of 16B
    #pragma unroll
    for (int u = tid; u < 512; u += 256) {
        const int row = u >> 4, seg = u & 15;
        const uint32_t off = (uint32_t)(row * X_STRIDE + seg * 16);
        const __nv_bfloat16* gh = xh + (size_t)(k0 + row) * D_ + seg * 8;
        const __nv_bfloat16* gl = xl + (size_t)(k0 + row) * D_ + seg * 8;
        cp_async16(sbase + 2 * W_TILE_B + off, gh);
        cp_async16(sbase + 2 * W_TILE_B + X_TILE_B + off, gl);
    }
    asm volatile("cp.async.commit_group;" ::: "memory");
}

__global__ __launch_bounds__(256, 1)
void gemm_sigmoid_kernel(const float* __restrict__ bias,
                         const float* __restrict__ x) {
    extern __shared__ char smem[];
    const uint32_t sb = smem_u32(smem);
    const int tid = threadIdx.x;
    const int lane = tid & 31;
    const int warp = tid >> 5;
    const int wm = warp >> 2;          // 0..1  (64 rows each)
    const int wn = warp & 3;           // 0..3  (32 cols each)

    const int d0 = blockIdx.x * BN;
    const int t0 = blockIdx.y * BM;    // == chunk index * T_
    const int b = blockIdx.z;

    const __nv_bfloat16* Wh = g_Whi + (size_t)t0 * K_;
    const __nv_bfloat16* Wl = g_Wlo + (size_t)t0 * K_;
    const __nv_bfloat16* xh = g_xhi + (size_t)b * K_ * D_ + d0;
    const __nv_bfloat16* xl = g_xlo + (size_t)b * K_ * D_ + d0;

    float acc[4][4][4];
    #pragma unroll
    for (int i = 0; i < 4; i++)
        #pragma unroll
        for (int j = 0; j < 4; j++)
            #pragma unroll
            for (int q = 0; q < 4; q++) acc[i][j][q] = 0.0f;

    const int a_row_in = (lane & 15);
    const int a_kseg = (lane >> 4);
    const int b_krow = (lane & 15);
    const int b_nseg = (lane >> 4);

    // Prologue: fill NSTAGES-1 stages
    #pragma unroll
    for (int p = 0; p < NSTAGES - 1; p++)
        load_stage(sb + p * STAGE_B, Wh, Wl, xh, xl, p * BK, tid);

    for (int c = 0; c < NSTAGE_IT; c++) {
        // keep one commit per iteration so wait_group counts stay uniform
        asm volatile("cp.async.wait_group %0;" :: "n"(NSTAGES - 2) : "memory");
        __syncthreads();

        if (c + NSTAGES - 1 < NSTAGE_IT)
            load_stage(sb + ((c + NSTAGES - 1) % NSTAGES) * STAGE_B,
                       Wh, Wl, xh, xl, (c + NSTAGES - 1) * BK, tid);
        else
            asm volatile("cp.async.commit_group;" ::: "memory");

        const uint32_t st = sb + (c % NSTAGES) * STAGE_B;
        const uint32_t sWh = st;
        const uint32_t sWl = st + W_TILE_B;
        const uint32_t sXh = st + 2 * W_TILE_B;
        const uint32_t sXl = st + 2 * W_TILE_B + X_TILE_B;

        #pragma unroll
        for (int kk = 0; kk < 2; kk++) {  // two k16 steps
            uint32_t ahi[4][4], alo[4][4];
            #pragma unroll
            for (int i = 0; i < 4; i++) {
                const uint32_t aoff =
                    (uint32_t)((wm * 64 + i * 16 + a_row_in) * W_STRIDE +
                               kk * 32 + a_kseg * 16);
                ldm_x4(ahi[i], sWh + aoff);
                ldm_x4(alo[i], sWl + aoff);
            }
            uint32_t bhi[2][4], blo[2][4];
            #pragma unroll
            for (int j = 0; j < 2; j++) {
                const uint32_t boff =
                    (uint32_t)((kk * 16 + b_krow) * X_STRIDE +
                               (wn * 32 + j * 16 + b_nseg * 8) * 2);
                ldm_x4_t(bhi[j], sXh + boff);
                ldm_x4_t(blo[j], sXl + boff);
            }
            #pragma unroll
            for (int i = 0; i < 4; i++) {
                #pragma unroll
                for (int j2 = 0; j2 < 4; j2++) {
                    const int jp = j2 >> 1, h = (j2 & 1) * 2;
                    mma_bf16(acc[i][j2], ahi[i], bhi[jp][h], bhi[jp][h + 1]);
                    mma_bf16(acc[i][j2], ahi[i], blo[jp][h], blo[jp][h + 1]);
                    mma_bf16(acc[i][j2], alo[i], bhi[jp][h], bhi[jp][h + 1]);
                }
            }
        }
        __syncthreads();
    }

    // drain async engine before smem reuse
    asm volatile("cp.async.wait_group 0;" ::: "memory");
    __syncthreads();

    // ---- Epilogue: bias + sigmoid -> g_lam (gmem) + lam tile (smem) ----
    float* lamS = reinterpret_cast<float*>(smem);           // [128][132]
    float* auS = reinterpret_cast<float*>(smem + LAM_BYTES); // [128] float2

    const int gr = lane >> 2;
    const int gc = (lane & 3) * 2;
    float* lamB = g_lam + (size_t)b * K_ * D_;
    #pragma unroll
    for (int i = 0; i < 4; i++) {
        const int tr0 = wm * 64 + i * 16 + gr;     // local t
        const float bz0 = __ldg(&bias[t0 + tr0]);
        const float bz1 = __ldg(&bias[t0 + tr0 + 8]);
        #pragma unroll
        for (int j2 = 0; j2 < 4; j2++) {
            const int dc = wn * 32 + j2 * 8 + gc;  // local d
            float2 v0, v1;
            v0.x = 1.0f / (1.0f + __expf(-(acc[i][j2][0] + bz0)));
            v0.y = 1.0f / (1.0f + __expf(-(acc[i][j2][1] + bz0)));
            v1.x = 1.0f / (1.0f + __expf(-(acc[i][j2][2] + bz1)));
            v1.y = 1.0f / (1.0f + __expf(-(acc[i][j2][3] + bz1)));
            *reinterpret_cast<float2*>(
                &lamB[(size_t)(t0 + tr0) * D_ + d0 + dc]) = v0;
            *reinterpret_cast<float2*>(
                &lamB[(size_t)(t0 + tr0 + 8) * D_ + d0 + dc]) = v1;
            *reinterpret_cast<float2*>(&lamS[tr0 * LAM_STRIDE + dc]) = v0;
            *reinterpret_cast<float2*>(&lamS[(tr0 + 8) * LAM_STRIDE + dc]) = v1;
        }
    }
    __syncthreads();

    // ---- Fused scan pass 1: per d-column affine summary over t 0..127 ----
    {
        const int half = tid >> 7;       // 0: t 0..63, 1: t 64..127
        const int dc = tid & 127;
        const float* xcol = x + ((size_t)b * K_ + t0 + half * 64) * D_ + d0 + dc;
        float A = 1.0f, U = 0.0f;
        #pragma unroll 8
        for (int tt = 0; tt < 64; tt++) {
            const float l = lamS[(half * 64 + tt) * LAM_STRIDE + dc];
            const float xv = xcol[(size_t)tt * D_];
            U = fmaf(l, U - xv, xv);
            A *= l;
        }
        if (half == 1) {
            auS[dc * 2] = A;
            auS[dc * 2 + 1] = U;
        }
        __syncthreads();
        if (half == 0) {
            const float A2 = auS[dc * 2];
            const float U2 = auS[dc * 2 + 1];
            const size_t idx = ((size_t)b * CHUNKS + blockIdx.y) * D_ + d0 + dc;
            g_A[idx] = A2 * A;
            g_U[idx] = fmaf(A2, U, U2);
        }
    }
}

// ---------------------------------------------------------------------------
// Scan pass 2: per (b,d) scan chunk summaries -> carry-in
// ---------------------------------------------------------------------------
__global__ void scan_pass2() {
    const int g = blockIdx.x * blockDim.x + threadIdx.x;  // B*D
    const int d = g % D_;
    const int b = g / D_;
    float s = 0.0f;
    #pragma unroll
    for (int c = 0; c < CHUNKS; c++) {
        const size_t idx = ((size_t)(b * CHUNKS + c)) * D_ + d;
        g_carry[idx] = s;
        s = fmaf(g_A[idx], s, g_U[idx]);
    }
}

// ---------------------------------------------------------------------------
// Scan pass 3: re-run each chunk with correct carry-in (float2 vectorized)
// ---------------------------------------------------------------------------
__global__ void scan_pass3(const float* __restrict__ x, float* __restrict__ ys) {
    const int g = blockIdx.x * blockDim.x + threadIdx.x;  // B*CHUNKS*(D/2)
    const int dp = g % (D_ / 2);
    const int c = (g / (D_ / 2)) % CHUNKS;
    const int b = g / ((D_ / 2) * CHUNKS);
    const int d = dp * 2;

    const float2* carry2 = reinterpret_cast<const float2*>(
        &g_carry[((size_t)(b * CHUNKS + c)) * D_ + d]);
    float2 s = *carry2;
    const size_t base = ((size_t)b * K_ + (size_t)c * T_) * D_ + d;
    const float2* lam2 = reinterpret_cast<const float2*>(g_lam + base);
    const float2* x2 = reinterpret_cast<const float2*>(x + base);
    float2* y2 = reinterpret_cast<float2*>(ys + base);
    #pragma unroll 4
    for (int t = 0; t < T_; t++) {
        const float2 l = lam2[(size_t)t * (D_ / 2)];
        const float2 xv = x2[(size_t)t * (D_ / 2)];
        s.x = fmaf(l.x, s.x - xv.x, xv.x);
        s.y = fmaf(l.y, s.y - xv.y, xv.y);
        y2[(size_t)t * (D_ / 2)] = s;
    }
}

// ---------------------------------------------------------------------------
extern "C" void kernel_launch(void* const* d_in, const int* in_sizes, int n_in,
                              void* d_out, int out_size) {
    const float* x    = (const float*)d_in[0];  // [B, K, D]
    const float* W    = (const float*)d_in[1];  // [K, K]
    const float* bias = (const float*)d_in[2];  // [K]
    float* ys = (float*)d_out;                  // [B, K, D]

    static bool attr_set = false;
    if (!attr_set) {
        cudaFuncSetAttribute(gemm_sigmoid_kernel,
                             cudaFuncAttributeMaxDynamicSharedMemorySize,
                             SMEM_TOTAL);
        attr_set = true;
    }

    convert_W_kernel<<<(K_ * K_) / (256 * 4), 256>>>(W);
    convert_x_kernel<<<((size_t)B_ * K_ * D_) / (256 * 4), 256>>>(x);

    gemm_sigmoid_kernel<<<dim3(D_ / BN, K_ / BM, B_), 256, SMEM_TOTAL>>>(bias, x);

    scan_pass2<<<(B_ * D_) / 256, 256>>>();
    scan_pass3<<<(B_ * CHUNKS * D_ / 2) / 256, 256>>>(x, ys);
}

// round 5
// speedup vs baseline: 2.4378x; 2.4378x over previous
#include <cuda_runtime.h>
#include <cuda_fp16.h>
#include <cstdint>
#include <math.h>

// ---------------------------------------------------------------------------
// Problem constants
// ---------------------------------------------------------------------------
static constexpr int B_ = 8;
static constexpr int K_ = 2048;   // time / contraction dim
static constexpr int D_ = 1024;   // channel dim
static constexpr int CHUNKS = 16; // time chunks == t-tiles (BM)
static constexpr int T_ = K_ / CHUNKS;  // 128 == BM

// GEMM tiling: C[t, d] = sum_k W[t,k] * x[k,d]   per batch
static constexpr int BM = 128;   // t tile
static constexpr int BN = 128;   // d tile
static constexpr int BK = 32;    // k per stage
static constexpr int NSTAGE_IT = K_ / BK;  // 64
static constexpr int NSTAGES = 4;          // pipeline depth

// smem strides (bytes), padded for conflict-free ldmatrix
static constexpr int W_STRIDE = 80;    // 32 fp16 = 64B + 16B pad
static constexpr int X_STRIDE = 272;   // 128 fp16 = 256B + 16B pad
static constexpr int W_TILE_B = BM * W_STRIDE;        // 10240
static constexpr int X_TILE_B = BK * X_STRIDE;        // 8704
static constexpr int STAGE_B = W_TILE_B + X_TILE_B;   // 18944
static constexpr int SMEM_TOTAL = NSTAGES * STAGE_B;  // 75776

// epilogue smem reuse: lam tile [128][132] fp32 + AU scratch
static constexpr int LAM_STRIDE = 132;                // floats
static constexpr int LAM_BYTES = BM * LAM_STRIDE * 4; // 67584
static_assert(LAM_BYTES + 1024 <= SMEM_TOTAL, "epilogue fits");

// ---------------------------------------------------------------------------
// Device scratch (no cudaMalloc allowed)
// ---------------------------------------------------------------------------
__device__ __align__(256) __half g_Wh[(size_t)K_ * K_];
__device__ __align__(256) __half g_xh[(size_t)B_ * K_ * D_];
__device__ __align__(256) float g_lam[(size_t)B_ * K_ * D_];
__device__ __align__(256) float g_A[(size_t)B_ * CHUNKS * D_];
__device__ __align__(256) float g_U[(size_t)B_ * CHUNKS * D_];
__device__ __align__(256) float g_carry[(size_t)B_ * CHUNKS * D_];

// ---------------------------------------------------------------------------
// PTX helpers (baseline ISA only — target sm_103 has no 'a' features)
// ---------------------------------------------------------------------------
__device__ __forceinline__ uint32_t smem_u32(const void* p) {
    uint32_t a;
    asm("{ .reg .u64 t; cvta.to.shared.u64 t, %1; cvt.u32.u64 %0, t; }"
        : "=r"(a) : "l"(p));
    return a;
}

__device__ __forceinline__ void cp_async16(uint32_t dst, const void* src) {
    asm volatile("cp.async.cg.shared.global [%0], [%1], 16;"
                 :: "r"(dst), "l"(src));
}

__device__ __forceinline__ void ldm_x4(uint32_t* r, uint32_t addr) {
    asm volatile("ldmatrix.sync.aligned.m8n8.x4.shared.b16 {%0,%1,%2,%3}, [%4];"
                 : "=r"(r[0]), "=r"(r[1]), "=r"(r[2]), "=r"(r[3]) : "r"(addr));
}

__device__ __forceinline__ void ldm_x4_t(uint32_t* r, uint32_t addr) {
    asm volatile("ldmatrix.sync.aligned.m8n8.x4.trans.shared.b16 {%0,%1,%2,%3}, [%4];"
                 : "=r"(r[0]), "=r"(r[1]), "=r"(r[2]), "=r"(r[3]) : "r"(addr));
}

__device__ __forceinline__ void mma_f16(float* c, const uint32_t* a,
                                        const uint32_t b0, const uint32_t b1) {
    asm volatile(
        "mma.sync.aligned.m16n8k16.row.col.f32.f16.f16.f32 "
        "{%0,%1,%2,%3}, {%4,%5,%6,%7}, {%8,%9}, {%0,%1,%2,%3};"
        : "+f"(c[0]), "+f"(c[1]), "+f"(c[2]), "+f"(c[3])
        : "r"(a[0]), "r"(a[1]), "r"(a[2]), "r"(a[3]), "r"(b0), "r"(b1));
}

// ---------------------------------------------------------------------------
// Converters fp32 -> fp16
// ---------------------------------------------------------------------------
__global__ void convert_W_kernel(const float* __restrict__ W) {
    const size_t i = ((size_t)blockIdx.x * blockDim.x + threadIdx.x) * 4;
    float4 v = *reinterpret_cast<const float4*>(W + i);
    __half h[4];
    h[0] = __float2half(v.x); h[1] = __float2half(v.y);
    h[2] = __float2half(v.z); h[3] = __float2half(v.w);
    *reinterpret_cast<uint2*>(g_Wh + i) = *reinterpret_cast<uint2*>(h);
}

__global__ void convert_x_kernel(const float* __restrict__ x) {
    const size_t i = ((size_t)blockIdx.x * blockDim.x + threadIdx.x) * 4;
    float4 v = *reinterpret_cast<const float4*>(x + i);
    __half h[4];
    h[0] = __float2half(v.x); h[1] = __float2half(v.y);
    h[2] = __float2half(v.z); h[3] = __float2half(v.w);
    *reinterpret_cast<uint2*>(g_xh + i) = *reinterpret_cast<uint2*>(h);
}

// ---------------------------------------------------------------------------
// GEMM + sigmoid + fused per-chunk scan summary
// ---------------------------------------------------------------------------
__device__ __forceinline__ void load_stage(uint32_t sbase,
                                           const __half* Wp,
                                           const __half* xp,
                                           int k0, int tid) {
    // W tile: 128 rows x 4 segs of 16B
    #pragma unroll
    for (int u = tid; u < 512; u += 256) {
        const int row = u >> 2, seg = u & 3;
        const uint32_t off = (uint32_t)(row * W_STRIDE + seg * 16);
        cp_async16(sbase + off, Wp + (size_t)row * K_ + k0 + seg * 8);
    }
    // x tile: 32 rows x 16 segs of 16B
    #pragma unroll
    for (int u = tid; u < 512; u += 256) {
        const int row = u >> 4, seg = u & 15;
        const uint32_t off = (uint32_t)(row * X_STRIDE + seg * 16);
        cp_async16(sbase + W_TILE_B + off,
                   xp + (size_t)(k0 + row) * D_ + seg * 8);
    }
    asm volatile("cp.async.commit_group;" ::: "memory");
}

__global__ __launch_bounds__(256, 2)
void gemm_sigmoid_kernel(const float* __restrict__ bias,
                         const float* __restrict__ x) {
    extern __shared__ char smem[];
    const uint32_t sb = smem_u32(smem);
    const int tid = threadIdx.x;
    const int lane = tid & 31;
    const int warp = tid >> 5;
    const int wm = warp >> 2;          // 0..1  (64 rows each)
    const int wn = warp & 3;           // 0..3  (32 cols each)

    const int d0 = blockIdx.x * BN;
    const int t0 = blockIdx.y * BM;    // == chunk index * T_
    const int b = blockIdx.z;

    const __half* Wp = g_Wh + (size_t)t0 * K_;
    const __half* xp = g_xh + (size_t)b * K_ * D_ + d0;

    float acc[4][4][4];
    #pragma unroll
    for (int i = 0; i < 4; i++)
        #pragma unroll
        for (int j = 0; j < 4; j++)
            #pragma unroll
            for (int q = 0; q < 4; q++) acc[i][j][q] = 0.0f;

    const int a_row_in = (lane & 15);
    const int a_kseg = (lane >> 4);
    const int b_krow = (lane & 15);
    const int b_nseg = (lane >> 4);

    // Prologue: fill NSTAGES-1 stages
    #pragma unroll
    for (int p = 0; p < NSTAGES - 1; p++)
        load_stage(sb + p * STAGE_B, Wp, xp, p * BK, tid);

    for (int c = 0; c < NSTAGE_IT; c++) {
        asm volatile("cp.async.wait_group %0;" :: "n"(NSTAGES - 2) : "memory");
        __syncthreads();   // single barrier per stage (issue-after-sync safe)

        if (c + NSTAGES - 1 < NSTAGE_IT)
            load_stage(sb + ((c + NSTAGES - 1) % NSTAGES) * STAGE_B,
                       Wp, xp, (c + NSTAGES - 1) * BK, tid);
        else
            asm volatile("cp.async.commit_group;" ::: "memory");

        const uint32_t st = sb + (c % NSTAGES) * STAGE_B;
        const uint32_t sW = st;
        const uint32_t sX = st + W_TILE_B;

        #pragma unroll
        for (int kk = 0; kk < 2; kk++) {  // two k16 steps
            uint32_t af[4][4];
            #pragma unroll
            for (int i = 0; i < 4; i++) {
                const uint32_t aoff =
                    (uint32_t)((wm * 64 + i * 16 + a_row_in) * W_STRIDE +
                               kk * 32 + a_kseg * 16);
                ldm_x4(af[i], sW + aoff);
            }
            uint32_t bf[2][4];
            #pragma unroll
            for (int j = 0; j < 2; j++) {
                const uint32_t boff =
                    (uint32_t)((kk * 16 + b_krow) * X_STRIDE +
                               (wn * 32 + j * 16 + b_nseg * 8) * 2);
                ldm_x4_t(bf[j], sX + boff);
            }
            #pragma unroll
            for (int i = 0; i < 4; i++) {
                #pragma unroll
                for (int j2 = 0; j2 < 4; j2++) {
                    const int jp = j2 >> 1, h = (j2 & 1) * 2;
                    mma_f16(acc[i][j2], af[i], bf[jp][h], bf[jp][h + 1]);
                }
            }
        }
    }

    // drain async engine before smem reuse
    asm volatile("cp.async.wait_group 0;" ::: "memory");
    __syncthreads();

    // ---- Epilogue: bias + sigmoid -> g_lam (gmem) + lam tile (smem) ----
    float* lamS = reinterpret_cast<float*>(smem);            // [128][132]
    float* auS = reinterpret_cast<float*>(smem + LAM_BYTES); // [128] float2

    const int gr = lane >> 2;
    const int gc = (lane & 3) * 2;
    float* lamB = g_lam + (size_t)b * K_ * D_;
    #pragma unroll
    for (int i = 0; i < 4; i++) {
        const int tr0 = wm * 64 + i * 16 + gr;     // local t
        const float bz0 = __ldg(&bias[t0 + tr0]);
        const float bz1 = __ldg(&bias[t0 + tr0 + 8]);
        #pragma unroll
        for (int j2 = 0; j2 < 4; j2++) {
            const int dc = wn * 32 + j2 * 8 + gc;  // local d
            float2 v0, v1;
            v0.x = 1.0f / (1.0f + __expf(-(acc[i][j2][0] + bz0)));
            v0.y = 1.0f / (1.0f + __expf(-(acc[i][j2][1] + bz0)));
            v1.x = 1.0f / (1.0f + __expf(-(acc[i][j2][2] + bz1)));
            v1.y = 1.0f / (1.0f + __expf(-(acc[i][j2][3] + bz1)));
            *reinterpret_cast<float2*>(
                &lamB[(size_t)(t0 + tr0) * D_ + d0 + dc]) = v0;
            *reinterpret_cast<float2*>(
                &lamB[(size_t)(t0 + tr0 + 8) * D_ + d0 + dc]) = v1;
            *reinterpret_cast<float2*>(&lamS[tr0 * LAM_STRIDE + dc]) = v0;
            *reinterpret_cast<float2*>(&lamS[(tr0 + 8) * LAM_STRIDE + dc]) = v1;
        }
    }
    __syncthreads();

    // ---- Fused scan pass 1: per d-column affine summary over t 0..127 ----
    {
        const int half = tid >> 7;       // 0: t 0..63, 1: t 64..127
        const int dc = tid & 127;
        const float* xcol = x + ((size_t)b * K_ + t0 + half * 64) * D_ + d0 + dc;
        float A = 1.0f, U = 0.0f;
        #pragma unroll 8
        for (int tt = 0; tt < 64; tt++) {
            const float l = lamS[(half * 64 + tt) * LAM_STRIDE + dc];
            const float xv = xcol[(size_t)tt * D_];
            U = fmaf(l, U - xv, xv);
            A *= l;
        }
        if (half == 1) {
            auS[dc * 2] = A;
            auS[dc * 2 + 1] = U;
        }
        __syncthreads();
        if (half == 0) {
            const float A2 = auS[dc * 2];
            const float U2 = auS[dc * 2 + 1];
            const size_t idx = ((size_t)b * CHUNKS + blockIdx.y) * D_ + d0 + dc;
            g_A[idx] = A2 * A;
            g_U[idx] = fmaf(A2, U, U2);
        }
    }
}

// ---------------------------------------------------------------------------
// Scan pass 2: per (b,d) scan chunk summaries -> carry-in
// ---------------------------------------------------------------------------
__global__ void scan_pass2() {
    const int g = blockIdx.x * blockDim.x + threadIdx.x;  // B*D
    const int d = g % D_;
    const int b = g / D_;
    float s = 0.0f;
    #pragma unroll
    for (int c = 0; c < CHUNKS; c++) {
        const size_t idx = ((size_t)(b * CHUNKS + c)) * D_ + d;
        g_carry[idx] = s;
        s = fmaf(g_A[idx], s, g_U[idx]);
    }
}

// ---------------------------------------------------------------------------
// Scan pass 3: re-run each chunk with correct carry-in (float2 vectorized)
// ---------------------------------------------------------------------------
__global__ void scan_pass3(const float* __restrict__ x, float* __restrict__ ys) {
    const int g = blockIdx.x * blockDim.x + threadIdx.x;  // B*CHUNKS*(D/2)
    const int dp = g % (D_ / 2);
    const int c = (g / (D_ / 2)) % CHUNKS;
    const int b = g / ((D_ / 2) * CHUNKS);
    const int d = dp * 2;

    const float2* carry2 = reinterpret_cast<const float2*>(
        &g_carry[((size_t)(b * CHUNKS + c)) * D_ + d]);
    float2 s = *carry2;
    const size_t base = ((size_t)b * K_ + (size_t)c * T_) * D_ + d;
    const float2* lam2 = reinterpret_cast<const float2*>(g_lam + base);
    const float2* x2 = reinterpret_cast<const float2*>(x + base);
    float2* y2 = reinterpret_cast<float2*>(ys + base);
    #pragma unroll 4
    for (int t = 0; t < T_; t++) {
        const float2 l = lam2[(size_t)t * (D_ / 2)];
        const float2 xv = x2[(size_t)t * (D_ / 2)];
        s.x = fmaf(l.x, s.x - xv.x, xv.x);
        s.y = fmaf(l.y, s.y - xv.y, xv.y);
        y2[(size_t)t * (D_ / 2)] = s;
    }
}

// ---------------------------------------------------------------------------
extern "C" void kernel_launch(void* const* d_in, const int* in_sizes, int n_in,
                              void* d_out, int out_size) {
    const float* x    = (const float*)d_in[0];  // [B, K, D]
    const float* W    = (const float*)d_in[1];  // [K, K]
    const float* bias = (const float*)d_in[2];  // [K]
    float* ys = (float*)d_out;                  // [B, K, D]

    static bool attr_set = false;
    if (!attr_set) {
        cudaFuncSetAttribute(gemm_sigmoid_kernel,
                             cudaFuncAttributeMaxDynamicSharedMemorySize,
                             SMEM_TOTAL);
        attr_set = true;
    }

    convert_W_kernel<<<(K_ * K_) / (256 * 4), 256>>>(W);
    convert_x_kernel<<<((size_t)B_ * K_ * D_) / (256 * 4), 256>>>(x);

    gemm_sigmoid_kernel<<<dim3(D_ / BN, K_ / BM, B_), 256, SMEM_TOTAL>>>(bias, x);

    scan_pass2<<<(B_ * D_) / 256, 256>>>();
    scan_pass3<<<(B_ * CHUNKS * D_ / 2) / 256, 256>>>(x, ys);
}

// round 6
// speedup vs baseline: 2.4743x; 1.0150x over previous
#include <cuda_runtime.h>
#include <cuda_fp16.h>
#include <cstdint>
#include <math.h>

// ---------------------------------------------------------------------------
// Problem constants
// ---------------------------------------------------------------------------
static constexpr int B_ = 8;
static constexpr int K_ = 2048;   // time / contraction dim
static constexpr int D_ = 1024;   // channel dim
static constexpr int CH2 = 32;    // half-chunks (T2 = 64 steps each)
static constexpr int T2 = K_ / CH2;  // 64

// GEMM tiling: C[t, d] = sum_k W[t,k] * x[k,d]   per batch
static constexpr int BM = 128;   // t tile (= 2 half-chunks)
static constexpr int BN = 128;   // d tile
static constexpr int BK = 32;    // k per stage
static constexpr int NSTAGE_IT = K_ / BK;  // 64
static constexpr int NSTAGES = 4;          // pipeline depth

// smem strides (bytes), padded for conflict-free ldmatrix
static constexpr int W_STRIDE = 80;    // 32 fp16 = 64B + 16B pad
static constexpr int X_STRIDE = 272;   // 128 fp16 = 256B + 16B pad
static constexpr int W_TILE_B = BM * W_STRIDE;        // 10240
static constexpr int X_TILE_B = BK * X_STRIDE;        // 8704
static constexpr int STAGE_B = W_TILE_B + X_TILE_B;   // 18944
static constexpr int SMEM_TOTAL = NSTAGES * STAGE_B;  // 75776

// epilogue smem reuse: lam tile [128][132] fp32
static constexpr int LAM_STRIDE = 132;                // floats
static constexpr int LAM_BYTES = BM * LAM_STRIDE * 4; // 67584
static_assert(LAM_BYTES <= SMEM_TOTAL, "epilogue fits");

// ---------------------------------------------------------------------------
// Device scratch (no cudaMalloc allowed)
// ---------------------------------------------------------------------------
__device__ __align__(256) __half g_Wh[(size_t)K_ * K_];
__device__ __align__(256) __half g_xh[(size_t)B_ * K_ * D_];
__device__ __align__(256) float g_lam[(size_t)B_ * K_ * D_];
__device__ __align__(256) float g_A[(size_t)B_ * CH2 * D_];   // half-chunk prod
__device__ __align__(256) float g_U[(size_t)B_ * CH2 * D_];   // half-chunk off

// ---------------------------------------------------------------------------
// PTX helpers (baseline ISA only — target sm_103 has no 'a' features)
// ---------------------------------------------------------------------------
__device__ __forceinline__ uint32_t smem_u32(const void* p) {
    uint32_t a;
    asm("{ .reg .u64 t; cvta.to.shared.u64 t, %1; cvt.u32.u64 %0, t; }"
        : "=r"(a) : "l"(p));
    return a;
}

__device__ __forceinline__ void cp_async16(uint32_t dst, const void* src) {
    asm volatile("cp.async.cg.shared.global [%0], [%1], 16;"
                 :: "r"(dst), "l"(src));
}

__device__ __forceinline__ void ldm_x4(uint32_t* r, uint32_t addr) {
    asm volatile("ldmatrix.sync.aligned.m8n8.x4.shared.b16 {%0,%1,%2,%3}, [%4];"
                 : "=r"(r[0]), "=r"(r[1]), "=r"(r[2]), "=r"(r[3]) : "r"(addr));
}

__device__ __forceinline__ void ldm_x4_t(uint32_t* r, uint32_t addr) {
    asm volatile("ldmatrix.sync.aligned.m8n8.x4.trans.shared.b16 {%0,%1,%2,%3}, [%4];"
                 : "=r"(r[0]), "=r"(r[1]), "=r"(r[2]), "=r"(r[3]) : "r"(addr));
}

__device__ __forceinline__ void mma_f16(float* c, const uint32_t* a,
                                        const uint32_t b0, const uint32_t b1) {
    asm volatile(
        "mma.sync.aligned.m16n8k16.row.col.f32.f16.f16.f32 "
        "{%0,%1,%2,%3}, {%4,%5,%6,%7}, {%8,%9}, {%0,%1,%2,%3};"
        : "+f"(c[0]), "+f"(c[1]), "+f"(c[2]), "+f"(c[3])
        : "r"(a[0]), "r"(a[1]), "r"(a[2]), "r"(a[3]), "r"(b0), "r"(b1));
}

// ---------------------------------------------------------------------------
// Converters fp32 -> fp16
// ---------------------------------------------------------------------------
__global__ void convert_W_kernel(const float* __restrict__ W) {
    const size_t i = ((size_t)blockIdx.x * blockDim.x + threadIdx.x) * 4;
    float4 v = *reinterpret_cast<const float4*>(W + i);
    __half h[4];
    h[0] = __float2half(v.x); h[1] = __float2half(v.y);
    h[2] = __float2half(v.z); h[3] = __float2half(v.w);
    *reinterpret_cast<uint2*>(g_Wh + i) = *reinterpret_cast<uint2*>(h);
}

__global__ void convert_x_kernel(const float* __restrict__ x) {
    const size_t i = ((size_t)blockIdx.x * blockDim.x + threadIdx.x) * 4;
    float4 v = *reinterpret_cast<const float4*>(x + i);
    __half h[4];
    h[0] = __float2half(v.x); h[1] = __float2half(v.y);
    h[2] = __float2half(v.z); h[3] = __float2half(v.w);
    *reinterpret_cast<uint2*>(g_xh + i) = *reinterpret_cast<uint2*>(h);
}

// ---------------------------------------------------------------------------
// GEMM + sigmoid + fused half-chunk scan summaries
// ---------------------------------------------------------------------------
__device__ __forceinline__ void load_stage(uint32_t sbase,
                                           const __half* Wp,
                                           const __half* xp,
                                           int k0, int tid) {
    #pragma unroll
    for (int u = tid; u < 512; u += 256) {
        const int row = u >> 2, seg = u & 3;
        const uint32_t off = (uint32_t)(row * W_STRIDE + seg * 16);
        cp_async16(sbase + off, Wp + (size_t)row * K_ + k0 + seg * 8);
    }
    #pragma unroll
    for (int u = tid; u < 512; u += 256) {
        const int row = u >> 4, seg = u & 15;
        const uint32_t off = (uint32_t)(row * X_STRIDE + seg * 16);
        cp_async16(sbase + W_TILE_B + off,
                   xp + (size_t)(k0 + row) * D_ + seg * 8);
    }
    asm volatile("cp.async.commit_group;" ::: "memory");
}

__global__ __launch_bounds__(256, 2)
void gemm_sigmoid_kernel(const float* __restrict__ bias,
                         const float* __restrict__ x) {
    extern __shared__ char smem[];
    const uint32_t sb = smem_u32(smem);
    const int tid = threadIdx.x;
    const int lane = tid & 31;
    const int warp = tid >> 5;
    const int wm = warp >> 2;          // 0..1  (64 rows each)
    const int wn = warp & 3;           // 0..3  (32 cols each)

    const int d0 = blockIdx.x * BN;
    const int t0 = blockIdx.y * BM;
    const int b = blockIdx.z;

    const __half* Wp = g_Wh + (size_t)t0 * K_;
    const __half* xp = g_xh + (size_t)b * K_ * D_ + d0;

    float acc[4][4][4];
    #pragma unroll
    for (int i = 0; i < 4; i++)
        #pragma unroll
        for (int j = 0; j < 4; j++)
            #pragma unroll
            for (int q = 0; q < 4; q++) acc[i][j][q] = 0.0f;

    const int a_row_in = (lane & 15);
    const int a_kseg = (lane >> 4);
    const int b_krow = (lane & 15);
    const int b_nseg = (lane >> 4);

    #pragma unroll
    for (int p = 0; p < NSTAGES - 1; p++)
        load_stage(sb + p * STAGE_B, Wp, xp, p * BK, tid);

    for (int c = 0; c < NSTAGE_IT; c++) {
        asm volatile("cp.async.wait_group %0;" :: "n"(NSTAGES - 2) : "memory");
        __syncthreads();

        if (c + NSTAGES - 1 < NSTAGE_IT)
            load_stage(sb + ((c + NSTAGES - 1) % NSTAGES) * STAGE_B,
                       Wp, xp, (c + NSTAGES - 1) * BK, tid);
        else
            asm volatile("cp.async.commit_group;" ::: "memory");

        const uint32_t st = sb + (c % NSTAGES) * STAGE_B;
        const uint32_t sW = st;
        const uint32_t sX = st + W_TILE_B;

        #pragma unroll
        for (int kk = 0; kk < 2; kk++) {
            uint32_t af[4][4];
            #pragma unroll
            for (int i = 0; i < 4; i++) {
                const uint32_t aoff =
                    (uint32_t)((wm * 64 + i * 16 + a_row_in) * W_STRIDE +
                               kk * 32 + a_kseg * 16);
                ldm_x4(af[i], sW + aoff);
            }
            uint32_t bf[2][4];
            #pragma unroll
            for (int j = 0; j < 2; j++) {
                const uint32_t boff =
                    (uint32_t)((kk * 16 + b_krow) * X_STRIDE +
                               (wn * 32 + j * 16 + b_nseg * 8) * 2);
                ldm_x4_t(bf[j], sX + boff);
            }
            #pragma unroll
            for (int i = 0; i < 4; i++) {
                #pragma unroll
                for (int j2 = 0; j2 < 4; j2++) {
                    const int jp = j2 >> 1, h = (j2 & 1) * 2;
                    mma_f16(acc[i][j2], af[i], bf[jp][h], bf[jp][h + 1]);
                }
            }
        }
    }

    // drain async engine before smem reuse
    asm volatile("cp.async.wait_group 0;" ::: "memory");
    __syncthreads();

    // ---- Epilogue phase 1: bias + sigmoid -> lam tile in smem ----
    float* lamS = reinterpret_cast<float*>(smem);            // [128][132]
    const int gr = lane >> 2;
    const int gc = (lane & 3) * 2;
    #pragma unroll
    for (int i = 0; i < 4; i++) {
        const int tr0 = wm * 64 + i * 16 + gr;
        const float bz0 = __ldg(&bias[t0 + tr0]);
        const float bz1 = __ldg(&bias[t0 + tr0 + 8]);
        #pragma unroll
        for (int j2 = 0; j2 < 4; j2++) {
            const int dc = wn * 32 + j2 * 8 + gc;
            float2 v0, v1;
            v0.x = 1.0f / (1.0f + __expf(-(acc[i][j2][0] + bz0)));
            v0.y = 1.0f / (1.0f + __expf(-(acc[i][j2][1] + bz0)));
            v1.x = 1.0f / (1.0f + __expf(-(acc[i][j2][2] + bz1)));
            v1.y = 1.0f / (1.0f + __expf(-(acc[i][j2][3] + bz1)));
            *reinterpret_cast<float2*>(&lamS[tr0 * LAM_STRIDE + dc]) = v0;
            *reinterpret_cast<float2*>(&lamS[(tr0 + 8) * LAM_STRIDE + dc]) = v1;
        }
    }
    __syncthreads();

    // ---- Epilogue phase 2a: coalesced float4 store of lam to gmem ----
    float* lamB = g_lam + ((size_t)b * K_ + t0) * D_ + d0;
    #pragma unroll
    for (int u = tid; u < BM * (BN / 4); u += 256) {  // 4096 float4
        const int row = u >> 5;          // 0..127
        const int col4 = (u & 31) * 4;   // 0..124
        const float4 v = *reinterpret_cast<const float4*>(
            &lamS[row * LAM_STRIDE + col4]);
        *reinterpret_cast<float4*>(&lamB[(size_t)row * D_ + col4]) = v;
    }

    // ---- Epilogue phase 2b: per-half affine summaries (T2=64 each) ----
    {
        const int half = tid >> 7;       // 0: t 0..63, 1: t 64..127
        const int dc = tid & 127;
        const float* xcol = x + ((size_t)b * K_ + t0 + half * 64) * D_ + d0 + dc;
        float A = 1.0f, U = 0.0f;
        #pragma unroll 8
        for (int tt = 0; tt < 64; tt++) {
            const float l = lamS[(half * 64 + tt) * LAM_STRIDE + dc];
            const float xv = xcol[(size_t)tt * D_];
            U = fmaf(l, U - xv, xv);
            A *= l;
        }
        const int c2 = blockIdx.y * 2 + half;   // half-chunk index 0..31
        const size_t idx = ((size_t)b * CH2 + c2) * D_ + d0 + dc;
        g_A[idx] = A;
        g_U[idx] = U;
    }
}

// ---------------------------------------------------------------------------
// Scan pass 3: per (b, half-chunk) block; carry computed in-register from
// half-chunk summaries (no separate pass 2). float4 lanes over d.
// ---------------------------------------------------------------------------
__global__ __launch_bounds__(256)
void scan_pass3(const float* __restrict__ x, float* __restrict__ ys) {
    const int c2 = blockIdx.x;           // 0..31
    const int b = blockIdx.y;            // 0..7
    const int d = threadIdx.x * 4;

    // carry = prefix of (A,U) over half-chunks < c2
    float4 s = make_float4(0.f, 0.f, 0.f, 0.f);
    for (int cc = 0; cc < c2; cc++) {
        const size_t idx = ((size_t)b * CH2 + cc) * D_ + d;
        const float4 A = *reinterpret_cast<const float4*>(&g_A[idx]);
        const float4 U = *reinterpret_cast<const float4*>(&g_U[idx]);
        s.x = fmaf(A.x, s.x, U.x);
        s.y = fmaf(A.y, s.y, U.y);
        s.z = fmaf(A.z, s.z, U.z);
        s.w = fmaf(A.w, s.w, U.w);
    }

    const size_t base = ((size_t)b * K_ + (size_t)c2 * T2) * D_ + d;
    const float4* lam4 = reinterpret_cast<const float4*>(g_lam + base);
    const float4* x4 = reinterpret_cast<const float4*>(x + base);
    float4* y4 = reinterpret_cast<float4*>(ys + base);
    #pragma unroll 4
    for (int t = 0; t < T2; t++) {
        const float4 l = lam4[(size_t)t * (D_ / 4)];
        const float4 xv = x4[(size_t)t * (D_ / 4)];
        s.x = fmaf(l.x, s.x - xv.x, xv.x);
        s.y = fmaf(l.y, s.y - xv.y, xv.y);
        s.z = fmaf(l.z, s.z - xv.z, xv.z);
        s.w = fmaf(l.w, s.w - xv.w, xv.w);
        y4[(size_t)t * (D_ / 4)] = s;
    }
}

// ---------------------------------------------------------------------------
extern "C" void kernel_launch(void* const* d_in, const int* in_sizes, int n_in,
                              void* d_out, int out_size) {
    const float* x    = (const float*)d_in[0];  // [B, K, D]
    const float* W    = (const float*)d_in[1];  // [K, K]
    const float* bias = (const float*)d_in[2];  // [K]
    float* ys = (float*)d_out;                  // [B, K, D]

    static bool attr_set = false;
    if (!attr_set) {
        cudaFuncSetAttribute(gemm_sigmoid_kernel,
                             cudaFuncAttributeMaxDynamicSharedMemorySize,
                             SMEM_TOTAL);
        attr_set = true;
    }

    convert_W_kernel<<<(K_ * K_) / (256 * 4), 256>>>(W);
    convert_x_kernel<<<((size_t)B_ * K_ * D_) / (256 * 4), 256>>>(x);

    gemm_sigmoid_kernel<<<dim3(D_ / BN, K_ / BM, B_), 256, SMEM_TOTAL>>>(bias, x);

    scan_pass3<<<dim3(CH2, B_), 256>>>(x, ys);
}

// round 7
// speedup vs baseline: 2.5071x; 1.0133x over previous
#include <cuda_runtime.h>
#include <cuda_fp16.h>
#include <cstdint>
#include <math.h>

// ---------------------------------------------------------------------------
// Problem constants
// ---------------------------------------------------------------------------
static constexpr int B_ = 8;
static constexpr int K_ = 2048;   // time / contraction dim
static constexpr int D_ = 1024;   // channel dim
static constexpr int CH2 = 32;    // half-chunks (T2 = 64 steps each)
static constexpr int T2 = K_ / CH2;  // 64

// GEMM tiling: C[t, d] = sum_k W[t,k] * x[k,d]   per batch
static constexpr int BM = 128;   // t tile (= 2 half-chunks)
static constexpr int BN = 128;   // d tile
static constexpr int BK = 32;    // k per stage
static constexpr int NSTAGE_IT = K_ / BK;  // 64
static constexpr int NSTAGES = 4;          // pipeline depth

// smem strides (bytes), padded for conflict-free ldmatrix
static constexpr int W_STRIDE = 80;    // 32 fp16 = 64B + 16B pad
static constexpr int X_STRIDE = 272;   // 128 fp16 = 256B + 16B pad
static constexpr int W_TILE_B = BM * W_STRIDE;        // 10240
static constexpr int X_TILE_B = BK * X_STRIDE;        // 8704
static constexpr int STAGE_B = W_TILE_B + X_TILE_B;   // 18944
static constexpr int SMEM_TOTAL = NSTAGES * STAGE_B;  // 75776

// epilogue smem reuse: lam tile [128][136] fp16
static constexpr int LAM_STRIDE = 136;                 // halves (272B rows)
static constexpr int LAM_BYTES = BM * LAM_STRIDE * 2;  // 34816
static_assert(LAM_BYTES <= SMEM_TOTAL, "epilogue fits");

// ---------------------------------------------------------------------------
// Device scratch (no cudaMalloc allowed)
// ---------------------------------------------------------------------------
__device__ __align__(256) __half g_Wh[(size_t)K_ * K_];
__device__ __align__(256) __half g_xh[(size_t)B_ * K_ * D_];
__device__ __align__(256) __half g_lam16[(size_t)B_ * K_ * D_];
__device__ __align__(256) float g_A[(size_t)B_ * CH2 * D_];   // half-chunk prod
__device__ __align__(256) float g_U[(size_t)B_ * CH2 * D_];   // half-chunk off

// ---------------------------------------------------------------------------
// PTX helpers (baseline ISA only — target sm_103 has no 'a' features)
// ---------------------------------------------------------------------------
__device__ __forceinline__ uint32_t smem_u32(const void* p) {
    uint32_t a;
    asm("{ .reg .u64 t; cvta.to.shared.u64 t, %1; cvt.u32.u64 %0, t; }"
        : "=r"(a) : "l"(p));
    return a;
}

__device__ __forceinline__ void cp_async16(uint32_t dst, const void* src) {
    asm volatile("cp.async.cg.shared.global [%0], [%1], 16;"
                 :: "r"(dst), "l"(src));
}

__device__ __forceinline__ void ldm_x4(uint32_t* r, uint32_t addr) {
    asm volatile("ldmatrix.sync.aligned.m8n8.x4.shared.b16 {%0,%1,%2,%3}, [%4];"
                 : "=r"(r[0]), "=r"(r[1]), "=r"(r[2]), "=r"(r[3]) : "r"(addr));
}

__device__ __forceinline__ void ldm_x4_t(uint32_t* r, uint32_t addr) {
    asm volatile("ldmatrix.sync.aligned.m8n8.x4.trans.shared.b16 {%0,%1,%2,%3}, [%4];"
                 : "=r"(r[0]), "=r"(r[1]), "=r"(r[2]), "=r"(r[3]) : "r"(addr));
}

__device__ __forceinline__ void mma_f16(float* c, const uint32_t* a,
                                        const uint32_t b0, const uint32_t b1) {
    asm volatile(
        "mma.sync.aligned.m16n8k16.row.col.f32.f16.f16.f32 "
        "{%0,%1,%2,%3}, {%4,%5,%6,%7}, {%8,%9}, {%0,%1,%2,%3};"
        : "+f"(c[0]), "+f"(c[1]), "+f"(c[2]), "+f"(c[3])
        : "r"(a[0]), "r"(a[1]), "r"(a[2]), "r"(a[3]), "r"(b0), "r"(b1));
}

// ---------------------------------------------------------------------------
// Converters fp32 -> fp16
// ---------------------------------------------------------------------------
__global__ void convert_W_kernel(const float* __restrict__ W) {
    const size_t i = ((size_t)blockIdx.x * blockDim.x + threadIdx.x) * 4;
    float4 v = *reinterpret_cast<const float4*>(W + i);
    __half h[4];
    h[0] = __float2half(v.x); h[1] = __float2half(v.y);
    h[2] = __float2half(v.z); h[3] = __float2half(v.w);
    *reinterpret_cast<uint2*>(g_Wh + i) = *reinterpret_cast<uint2*>(h);
}

__global__ void convert_x_kernel(const float* __restrict__ x) {
    const size_t i = ((size_t)blockIdx.x * blockDim.x + threadIdx.x) * 4;
    float4 v = *reinterpret_cast<const float4*>(x + i);
    __half h[4];
    h[0] = __float2half(v.x); h[1] = __float2half(v.y);
    h[2] = __float2half(v.z); h[3] = __float2half(v.w);
    *reinterpret_cast<uint2*>(g_xh + i) = *reinterpret_cast<uint2*>(h);
}

// ---------------------------------------------------------------------------
// GEMM + sigmoid + fused half-chunk scan summaries (lam stored fp16)
// ---------------------------------------------------------------------------
__device__ __forceinline__ void load_stage(uint32_t sbase,
                                           const __half* Wp,
                                           const __half* xp,
                                           int k0, int tid) {
    #pragma unroll
    for (int u = tid; u < 512; u += 256) {
        const int row = u >> 2, seg = u & 3;
        const uint32_t off = (uint32_t)(row * W_STRIDE + seg * 16);
        cp_async16(sbase + off, Wp + (size_t)row * K_ + k0 + seg * 8);
    }
    #pragma unroll
    for (int u = tid; u < 512; u += 256) {
        const int row = u >> 4, seg = u & 15;
        const uint32_t off = (uint32_t)(row * X_STRIDE + seg * 16);
        cp_async16(sbase + W_TILE_B + off,
                   xp + (size_t)(k0 + row) * D_ + seg * 8);
    }
    asm volatile("cp.async.commit_group;" ::: "memory");
}

__global__ __launch_bounds__(256, 2)
void gemm_sigmoid_kernel(const float* __restrict__ bias,
                         const float* __restrict__ x) {
    extern __shared__ char smem[];
    const uint32_t sb = smem_u32(smem);
    const int tid = threadIdx.x;
    const int lane = tid & 31;
    const int warp = tid >> 5;
    const int wm = warp >> 2;          // 0..1  (64 rows each)
    const int wn = warp & 3;           // 0..3  (32 cols each)

    const int d0 = blockIdx.x * BN;
    const int t0 = blockIdx.y * BM;
    const int b = blockIdx.z;

    const __half* Wp = g_Wh + (size_t)t0 * K_;
    const __half* xp = g_xh + (size_t)b * K_ * D_ + d0;

    float acc[4][4][4];
    #pragma unroll
    for (int i = 0; i < 4; i++)
        #pragma unroll
        for (int j = 0; j < 4; j++)
            #pragma unroll
            for (int q = 0; q < 4; q++) acc[i][j][q] = 0.0f;

    const int a_row_in = (lane & 15);
    const int a_kseg = (lane >> 4);
    const int b_krow = (lane & 15);
    const int b_nseg = (lane >> 4);

    #pragma unroll
    for (int p = 0; p < NSTAGES - 1; p++)
        load_stage(sb + p * STAGE_B, Wp, xp, p * BK, tid);

    for (int c = 0; c < NSTAGE_IT; c++) {
        asm volatile("cp.async.wait_group %0;" :: "n"(NSTAGES - 2) : "memory");
        __syncthreads();

        if (c + NSTAGES - 1 < NSTAGE_IT)
            load_stage(sb + ((c + NSTAGES - 1) % NSTAGES) * STAGE_B,
                       Wp, xp, (c + NSTAGES - 1) * BK, tid);
        else
            asm volatile("cp.async.commit_group;" ::: "memory");

        const uint32_t st = sb + (c % NSTAGES) * STAGE_B;
        const uint32_t sW = st;
        const uint32_t sX = st + W_TILE_B;

        #pragma unroll
        for (int kk = 0; kk < 2; kk++) {
            uint32_t af[4][4];
            #pragma unroll
            for (int i = 0; i < 4; i++) {
                const uint32_t aoff =
                    (uint32_t)((wm * 64 + i * 16 + a_row_in) * W_STRIDE +
                               kk * 32 + a_kseg * 16);
                ldm_x4(af[i], sW + aoff);
            }
            uint32_t bf[2][4];
            #pragma unroll
            for (int j = 0; j < 2; j++) {
                const uint32_t boff =
                    (uint32_t)((kk * 16 + b_krow) * X_STRIDE +
                               (wn * 32 + j * 16 + b_nseg * 8) * 2);
                ldm_x4_t(bf[j], sX + boff);
            }
            #pragma unroll
            for (int i = 0; i < 4; i++) {
                #pragma unroll
                for (int j2 = 0; j2 < 4; j2++) {
                    const int jp = j2 >> 1, h = (j2 & 1) * 2;
                    mma_f16(acc[i][j2], af[i], bf[jp][h], bf[jp][h + 1]);
                }
            }
        }
    }

    // drain async engine before smem reuse
    asm volatile("cp.async.wait_group 0;" ::: "memory");
    __syncthreads();

    // ---- Epilogue phase 1: bias + sigmoid -> fp16 lam tile in smem ----
    __half* lamS = reinterpret_cast<__half*>(smem);          // [128][136]
    const int gr = lane >> 2;
    const int gc = (lane & 3) * 2;
    #pragma unroll
    for (int i = 0; i < 4; i++) {
        const int tr0 = wm * 64 + i * 16 + gr;
        const float bz0 = __ldg(&bias[t0 + tr0]);
        const float bz1 = __ldg(&bias[t0 + tr0 + 8]);
        #pragma unroll
        for (int j2 = 0; j2 < 4; j2++) {
            const int dc = wn * 32 + j2 * 8 + gc;
            __half2 h0, h1;
            h0.x = __float2half(1.0f / (1.0f + __expf(-(acc[i][j2][0] + bz0))));
            h0.y = __float2half(1.0f / (1.0f + __expf(-(acc[i][j2][1] + bz0))));
            h1.x = __float2half(1.0f / (1.0f + __expf(-(acc[i][j2][2] + bz1))));
            h1.y = __float2half(1.0f / (1.0f + __expf(-(acc[i][j2][3] + bz1))));
            *reinterpret_cast<__half2*>(&lamS[tr0 * LAM_STRIDE + dc]) = h0;
            *reinterpret_cast<__half2*>(&lamS[(tr0 + 8) * LAM_STRIDE + dc]) = h1;
        }
    }
    __syncthreads();

    // ---- Epilogue phase 2a: coalesced uint4 store of fp16 lam to gmem ----
    __half* lamB = g_lam16 + ((size_t)b * K_ + t0) * D_ + d0;
    #pragma unroll
    for (int u = tid; u < BM * (BN / 8); u += 256) {  // 2048 uint4
        const int row = u >> 4;          // 0..127
        const int col8 = (u & 15) * 8;   // 0..120
        const uint4 v = *reinterpret_cast<const uint4*>(
            &lamS[row * LAM_STRIDE + col8]);
        *reinterpret_cast<uint4*>(&lamB[(size_t)row * D_ + col8]) = v;
    }

    // ---- Epilogue phase 2b: per-half affine summaries (quantized lam) ----
    {
        const int half = tid >> 7;       // 0: t 0..63, 1: t 64..127
        const int dc = tid & 127;
        const float* xcol = x + ((size_t)b * K_ + t0 + half * 64) * D_ + d0 + dc;
        float A = 1.0f, U = 0.0f;
        #pragma unroll 8
        for (int tt = 0; tt < 64; tt++) {
            const float l = __half2float(lamS[(half * 64 + tt) * LAM_STRIDE + dc]);
            const float xv = xcol[(size_t)tt * D_];
            U = fmaf(l, U - xv, xv);
            A *= l;
        }
        const int c2 = blockIdx.y * 2 + half;   // half-chunk index 0..31
        const size_t idx = ((size_t)b * CH2 + c2) * D_ + d0 + dc;
        g_A[idx] = A;
        g_U[idx] = U;
    }
}

// ---------------------------------------------------------------------------
// Scan pass 3: per (b, half-chunk, d-half) block; carry computed in-register
// from half-chunk summaries. 128 threads x float4 over 512 d each.
// Longest-prefix blocks launch first (reversed c2).
// ---------------------------------------------------------------------------
__global__ __launch_bounds__(128)
void scan_pass3(const float* __restrict__ x, float* __restrict__ ys) {
    const int c2 = CH2 - 1 - blockIdx.x;  // heavy blocks first
    const int b = blockIdx.z;
    const int d = blockIdx.y * 512 + threadIdx.x * 4;

    // carry = prefix of (A,U) over half-chunks < c2
    float4 s = make_float4(0.f, 0.f, 0.f, 0.f);
    for (int cc = 0; cc < c2; cc++) {
        const size_t idx = ((size_t)b * CH2 + cc) * D_ + d;
        const float4 A = *reinterpret_cast<const float4*>(&g_A[idx]);
        const float4 U = *reinterpret_cast<const float4*>(&g_U[idx]);
        s.x = fmaf(A.x, s.x, U.x);
        s.y = fmaf(A.y, s.y, U.y);
        s.z = fmaf(A.z, s.z, U.z);
        s.w = fmaf(A.w, s.w, U.w);
    }

    const size_t base = ((size_t)b * K_ + (size_t)c2 * T2) * D_ + d;
    const __half2* lam2 = reinterpret_cast<const __half2*>(g_lam16 + base);
    const float4* x4 = reinterpret_cast<const float4*>(x + base);
    float4* y4 = reinterpret_cast<float4*>(ys + base);
    #pragma unroll 4
    for (int t = 0; t < T2; t++) {
        const uint2 lraw = *reinterpret_cast<const uint2*>(
            &lam2[(size_t)t * (D_ / 2)]);
        const __half2 la = *reinterpret_cast<const __half2*>(&lraw.x);
        const __half2 lb = *reinterpret_cast<const __half2*>(&lraw.y);
        const float2 l01 = __half22float2(la);
        const float2 l23 = __half22float2(lb);
        const float4 xv = x4[(size_t)t * (D_ / 4)];
        s.x = fmaf(l01.x, s.x - xv.x, xv.x);
        s.y = fmaf(l01.y, s.y - xv.y, xv.y);
        s.z = fmaf(l23.x, s.z - xv.z, xv.z);
        s.w = fmaf(l23.y, s.w - xv.w, xv.w);
        y4[(size_t)t * (D_ / 4)] = s;
    }
}

// ---------------------------------------------------------------------------
extern "C" void kernel_launch(void* const* d_in, const int* in_sizes, int n_in,
                              void* d_out, int out_size) {
    const float* x    = (const float*)d_in[0];  // [B, K, D]
    const float* W    = (const float*)d_in[1];  // [K, K]
    const float* bias = (const float*)d_in[2];  // [K]
    float* ys = (float*)d_out;                  // [B, K, D]

    static bool attr_set = false;
    if (!attr_set) {
        cudaFuncSetAttribute(gemm_sigmoid_kernel,
                             cudaFuncAttributeMaxDynamicSharedMemorySize,
                             SMEM_TOTAL);
        attr_set = true;
    }

    convert_W_kernel<<<(K_ * K_) / (256 * 4), 256>>>(W);
    convert_x_kernel<<<((size_t)B_ * K_ * D_) / (256 * 4), 256>>>(x);

    gemm_sigmoid_kernel<<<dim3(D_ / BN, K_ / BM, B_), 256, SMEM_TOTAL>>>(bias, x);

    scan_pass3<<<dim3(CH2, 2, B_), 128>>>(x, ys);
}

// round 8
// speedup vs baseline: 2.6732x; 1.0663x over previous
#include <cuda_runtime.h>
#include <cuda_fp16.h>
#include <cstdint>
#include <math.h>

// ---------------------------------------------------------------------------
// Problem constants
// ---------------------------------------------------------------------------
static constexpr int B_ = 8;
static constexpr int K_ = 2048;   // time / contraction dim
static constexpr int D_ = 1024;   // channel dim
static constexpr int CH2 = 32;    // half-chunks (T2 = 64 steps each)
static constexpr int T2 = K_ / CH2;  // 64

// GEMM tiling: C[t, d] = sum_k W[t,k] * x[k,d]   per batch
static constexpr int BM = 128;   // t tile (= 2 half-chunks)
static constexpr int BN = 128;   // d tile
static constexpr int BK = 32;    // k per stage
static constexpr int NSTAGE_IT = K_ / BK;  // 64
static constexpr int NSTAGES = 4;          // pipeline depth

// smem strides (bytes), padded for conflict-free ldmatrix
static constexpr int W_STRIDE = 80;    // 32 fp16 = 64B + 16B pad
static constexpr int X_STRIDE = 272;   // 128 fp16 = 256B + 16B pad
static constexpr int W_TILE_B = BM * W_STRIDE;        // 10240
static constexpr int X_TILE_B = BK * X_STRIDE;        // 8704
static constexpr int STAGE_B = W_TILE_B + X_TILE_B;   // 18944
static constexpr int SMEM_TOTAL = NSTAGES * STAGE_B;  // 75776

// epilogue smem reuse: lam tile [128][136] fp16
static constexpr int LAM_STRIDE = 136;                 // halves (272B rows)
static constexpr int LAM_BYTES = BM * LAM_STRIDE * 2;  // 34816
static_assert(LAM_BYTES <= SMEM_TOTAL, "epilogue fits");

// ---------------------------------------------------------------------------
// Device scratch (no cudaMalloc allowed)
// ---------------------------------------------------------------------------
__device__ __align__(256) __half g_Wh[(size_t)K_ * K_];
__device__ __align__(256) __half g_xh[(size_t)B_ * K_ * D_];
__device__ __align__(256) __half g_lam16[(size_t)B_ * K_ * D_];
__device__ __align__(256) float g_A[(size_t)B_ * CH2 * D_];   // half-chunk prod
__device__ __align__(256) float g_U[(size_t)B_ * CH2 * D_];   // half-chunk off

// ---------------------------------------------------------------------------
// PTX helpers (baseline ISA only — target sm_103 has no 'a' features)
// ---------------------------------------------------------------------------
__device__ __forceinline__ uint32_t smem_u32(const void* p) {
    uint32_t a;
    asm("{ .reg .u64 t; cvta.to.shared.u64 t, %1; cvt.u32.u64 %0, t; }"
        : "=r"(a) : "l"(p));
    return a;
}

__device__ __forceinline__ void cp_async16(uint32_t dst, const void* src) {
    asm volatile("cp.async.cg.shared.global [%0], [%1], 16;"
                 :: "r"(dst), "l"(src));
}

__device__ __forceinline__ void ldm_x4(uint32_t* r, uint32_t addr) {
    asm volatile("ldmatrix.sync.aligned.m8n8.x4.shared.b16 {%0,%1,%2,%3}, [%4];"
                 : "=r"(r[0]), "=r"(r[1]), "=r"(r[2]), "=r"(r[3]) : "r"(addr));
}

__device__ __forceinline__ void ldm_x4_t(uint32_t* r, uint32_t addr) {
    asm volatile("ldmatrix.sync.aligned.m8n8.x4.trans.shared.b16 {%0,%1,%2,%3}, [%4];"
                 : "=r"(r[0]), "=r"(r[1]), "=r"(r[2]), "=r"(r[3]) : "r"(addr));
}

__device__ __forceinline__ void mma_f16(float* c, const uint32_t* a,
                                        const uint32_t b0, const uint32_t b1) {
    asm volatile(
        "mma.sync.aligned.m16n8k16.row.col.f32.f16.f16.f32 "
        "{%0,%1,%2,%3}, {%4,%5,%6,%7}, {%8,%9}, {%0,%1,%2,%3};"
        : "+f"(c[0]), "+f"(c[1]), "+f"(c[2]), "+f"(c[3])
        : "r"(a[0]), "r"(a[1]), "r"(a[2]), "r"(a[3]), "r"(b0), "r"(b1));
}

// ---------------------------------------------------------------------------
// Fused converter: fp32 -> fp16 for W (4M elems) then x (16M elems)
// ---------------------------------------------------------------------------
__global__ void convert_all_kernel(const float* __restrict__ W,
                                   const float* __restrict__ x) {
    const size_t gi = ((size_t)blockIdx.x * blockDim.x + threadIdx.x) * 4;
    const size_t WN = (size_t)K_ * K_;
    const float* src;
    __half* dst;
    size_t i;
    if (gi < WN) {
        src = W; dst = g_Wh; i = gi;
    } else {
        src = x; dst = g_xh; i = gi - WN;
    }
    float4 v = *reinterpret_cast<const float4*>(src + i);
    __half h[4];
    h[0] = __float2half(v.x); h[1] = __float2half(v.y);
    h[2] = __float2half(v.z); h[3] = __float2half(v.w);
    *reinterpret_cast<uint2*>(dst + i) = *reinterpret_cast<uint2*>(h);
}

// ---------------------------------------------------------------------------
// GEMM + sigmoid + fused half-chunk scan summaries (lam stored fp16)
// ---------------------------------------------------------------------------
__device__ __forceinline__ void load_stage(uint32_t sbase,
                                           const __half* Wp,
                                           const __half* xp,
                                           int k0, int tid) {
    #pragma unroll
    for (int u = tid; u < 512; u += 256) {
        const int row = u >> 2, seg = u & 3;
        const uint32_t off = (uint32_t)(row * W_STRIDE + seg * 16);
        cp_async16(sbase + off, Wp + (size_t)row * K_ + k0 + seg * 8);
    }
    #pragma unroll
    for (int u = tid; u < 512; u += 256) {
        const int row = u >> 4, seg = u & 15;
        const uint32_t off = (uint32_t)(row * X_STRIDE + seg * 16);
        cp_async16(sbase + W_TILE_B + off,
                   xp + (size_t)(k0 + row) * D_ + seg * 8);
    }
    asm volatile("cp.async.commit_group;" ::: "memory");
}

__global__ __launch_bounds__(256, 2)
void gemm_sigmoid_kernel(const float* __restrict__ bias) {
    extern __shared__ char smem[];
    const uint32_t sb = smem_u32(smem);
    const int tid = threadIdx.x;
    const int lane = tid & 31;
    const int warp = tid >> 5;
    const int wm = warp >> 2;          // 0..1  (64 rows each)
    const int wn = warp & 3;           // 0..3  (32 cols each)

    const int d0 = blockIdx.x * BN;
    const int t0 = blockIdx.y * BM;
    const int b = blockIdx.z;

    const __half* Wp = g_Wh + (size_t)t0 * K_;
    const __half* xp = g_xh + (size_t)b * K_ * D_ + d0;

    float acc[4][4][4];
    #pragma unroll
    for (int i = 0; i < 4; i++)
        #pragma unroll
        for (int j = 0; j < 4; j++)
            #pragma unroll
            for (int q = 0; q < 4; q++) acc[i][j][q] = 0.0f;

    const int a_row_in = (lane & 15);
    const int a_kseg = (lane >> 4);
    const int b_krow = (lane & 15);
    const int b_nseg = (lane >> 4);

    #pragma unroll
    for (int p = 0; p < NSTAGES - 1; p++)
        load_stage(sb + p * STAGE_B, Wp, xp, p * BK, tid);

    for (int c = 0; c < NSTAGE_IT; c++) {
        asm volatile("cp.async.wait_group %0;" :: "n"(NSTAGES - 2) : "memory");
        __syncthreads();

        if (c + NSTAGES - 1 < NSTAGE_IT)
            load_stage(sb + ((c + NSTAGES - 1) % NSTAGES) * STAGE_B,
                       Wp, xp, (c + NSTAGES - 1) * BK, tid);
        else
            asm volatile("cp.async.commit_group;" ::: "memory");

        const uint32_t st = sb + (c % NSTAGES) * STAGE_B;
        const uint32_t sW = st;
        const uint32_t sX = st + W_TILE_B;

        #pragma unroll
        for (int kk = 0; kk < 2; kk++) {
            uint32_t af[4][4];
            #pragma unroll
            for (int i = 0; i < 4; i++) {
                const uint32_t aoff =
                    (uint32_t)((wm * 64 + i * 16 + a_row_in) * W_STRIDE +
                               kk * 32 + a_kseg * 16);
                ldm_x4(af[i], sW + aoff);
            }
            uint32_t bf[2][4];
            #pragma unroll
            for (int j = 0; j < 2; j++) {
                const uint32_t boff =
                    (uint32_t)((kk * 16 + b_krow) * X_STRIDE +
                               (wn * 32 + j * 16 + b_nseg * 8) * 2);
                ldm_x4_t(bf[j], sX + boff);
            }
            #pragma unroll
            for (int i = 0; i < 4; i++) {
                #pragma unroll
                for (int j2 = 0; j2 < 4; j2++) {
                    const int jp = j2 >> 1, h = (j2 & 1) * 2;
                    mma_f16(acc[i][j2], af[i], bf[jp][h], bf[jp][h + 1]);
                }
            }
        }
    }

    // drain async engine before smem reuse
    asm volatile("cp.async.wait_group 0;" ::: "memory");
    __syncthreads();

    // ---- Epilogue phase 1: bias + sigmoid -> fp16 lam tile in smem ----
    __half* lamS = reinterpret_cast<__half*>(smem);          // [128][136]
    const int gr = lane >> 2;
    const int gc = (lane & 3) * 2;
    #pragma unroll
    for (int i = 0; i < 4; i++) {
        const int tr0 = wm * 64 + i * 16 + gr;
        const float bz0 = __ldg(&bias[t0 + tr0]);
        const float bz1 = __ldg(&bias[t0 + tr0 + 8]);
        #pragma unroll
        for (int j2 = 0; j2 < 4; j2++) {
            const int dc = wn * 32 + j2 * 8 + gc;
            __half2 h0, h1;
            h0.x = __float2half(1.0f / (1.0f + __expf(-(acc[i][j2][0] + bz0))));
            h0.y = __float2half(1.0f / (1.0f + __expf(-(acc[i][j2][1] + bz0))));
            h1.x = __float2half(1.0f / (1.0f + __expf(-(acc[i][j2][2] + bz1))));
            h1.y = __float2half(1.0f / (1.0f + __expf(-(acc[i][j2][3] + bz1))));
            *reinterpret_cast<__half2*>(&lamS[tr0 * LAM_STRIDE + dc]) = h0;
            *reinterpret_cast<__half2*>(&lamS[(tr0 + 8) * LAM_STRIDE + dc]) = h1;
        }
    }
    __syncthreads();

    // ---- Epilogue phase 2a: coalesced uint4 store of fp16 lam to gmem ----
    __half* lamB = g_lam16 + ((size_t)b * K_ + t0) * D_ + d0;
    #pragma unroll
    for (int u = tid; u < BM * (BN / 8); u += 256) {  // 2048 uint4
        const int row = u >> 4;          // 0..127
        const int col8 = (u & 15) * 8;   // 0..120
        const uint4 v = *reinterpret_cast<const uint4*>(
            &lamS[row * LAM_STRIDE + col8]);
        *reinterpret_cast<uint4*>(&lamB[(size_t)row * D_ + col8]) = v;
    }

    // ---- Epilogue phase 2b: per-half affine summaries (quantized lam+x) ----
    {
        const int half = tid >> 7;       // 0: t 0..63, 1: t 64..127
        const int dc = tid & 127;
        const __half* xcol = g_xh +
            ((size_t)b * K_ + t0 + half * 64) * D_ + d0 + dc;
        float A = 1.0f, U = 0.0f;
        #pragma unroll 8
        for (int tt = 0; tt < 64; tt++) {
            const float l = __half2float(lamS[(half * 64 + tt) * LAM_STRIDE + dc]);
            const float xv = __half2float(xcol[(size_t)tt * D_]);
            U = fmaf(l, U - xv, xv);
            A *= l;
        }
        const int c2 = blockIdx.y * 2 + half;   // half-chunk index 0..31
        const size_t idx = ((size_t)b * CH2 + c2) * D_ + d0 + dc;
        g_A[idx] = A;
        g_U[idx] = U;
    }
}

// ---------------------------------------------------------------------------
// Scan pass 3: per (b, half-chunk, d-half) block; carry computed in-register
// from half-chunk summaries. 128 threads x float4 over 512 d each.
// fp16 x + fp16 lam reads, unroll-8 for MLP. Heavy blocks launch first.
// ---------------------------------------------------------------------------
__global__ __launch_bounds__(128)
void scan_pass3(float* __restrict__ ys) {
    const int c2 = CH2 - 1 - blockIdx.x;  // heavy blocks first
    const int b = blockIdx.z;
    const int d = blockIdx.y * 512 + threadIdx.x * 4;

    // carry = prefix of (A,U) over half-chunks < c2 (affine compose, unrolled)
    float4 s = make_float4(0.f, 0.f, 0.f, 0.f);
    #pragma unroll 4
    for (int cc = 0; cc < c2; cc++) {
        const size_t idx = ((size_t)b * CH2 + cc) * D_ + d;
        const float4 A = *reinterpret_cast<const float4*>(&g_A[idx]);
        const float4 U = *reinterpret_cast<const float4*>(&g_U[idx]);
        s.x = fmaf(A.x, s.x, U.x);
        s.y = fmaf(A.y, s.y, U.y);
        s.z = fmaf(A.z, s.z, U.z);
        s.w = fmaf(A.w, s.w, U.w);
    }

    const size_t base = ((size_t)b * K_ + (size_t)c2 * T2) * D_ + d;
    const uint2* lam2 = reinterpret_cast<const uint2*>(g_lam16 + base);
    const uint2* x2 = reinterpret_cast<const uint2*>(g_xh + base);
    float4* y4 = reinterpret_cast<float4*>(ys + base);
    #pragma unroll 8
    for (int t = 0; t < T2; t++) {
        const uint2 lraw = lam2[(size_t)t * (D_ / 4)];
        const uint2 xraw = x2[(size_t)t * (D_ / 4)];
        const float2 l01 = __half22float2(*reinterpret_cast<const __half2*>(&lraw.x));
        const float2 l23 = __half22float2(*reinterpret_cast<const __half2*>(&lraw.y));
        const float2 x01 = __half22float2(*reinterpret_cast<const __half2*>(&xraw.x));
        const float2 x23 = __half22float2(*reinterpret_cast<const __half2*>(&xraw.y));
        s.x = fmaf(l01.x, s.x - x01.x, x01.x);
        s.y = fmaf(l01.y, s.y - x01.y, x01.y);
        s.z = fmaf(l23.x, s.z - x23.x, x23.x);
        s.w = fmaf(l23.y, s.w - x23.y, x23.y);
        y4[(size_t)t * (D_ / 4)] = s;
    }
}

// ---------------------------------------------------------------------------
extern "C" void kernel_launch(void* const* d_in, const int* in_sizes, int n_in,
                              void* d_out, int out_size) {
    const float* x    = (const float*)d_in[0];  // [B, K, D]
    const float* W    = (const float*)d_in[1];  // [K, K]
    const float* bias = (const float*)d_in[2];  // [K]
    float* ys = (float*)d_out;                  // [B, K, D]

    static bool attr_set = false;
    if (!attr_set) {
        cudaFuncSetAttribute(gemm_sigmoid_kernel,
                             cudaFuncAttributeMaxDynamicSharedMemorySize,
                             SMEM_TOTAL);
        attr_set = true;
    }

    const size_t total_conv = (size_t)K_ * K_ + (size_t)B_ * K_ * D_;  // 20M
    convert_all_kernel<<<(int)(total_conv / (256 * 4)), 256>>>(W, x);

    gemm_sigmoid_kernel<<<dim3(D_ / BN, K_ / BM, B_), 256, SMEM_TOTAL>>>(bias);

    scan_pass3<<<dim3(CH2, 2, B_), 128>>>(ys);
}